// round 16
// baseline (speedup 1.0000x reference)
#include <cuda_runtime.h>
#include <cuda_fp16.h>
#include <cstdint>

// out[b,o] = ( x @ softmax(W,axis=1)^T > 0.5 )
// Two-pass: (1) HMMA fp16 two-limb GEMM (scale 2^16, fp32 accum) decides all
// outputs with |S1 - 32768| > 0.6 (provably matches the reference fp32 serial
// chain); (2) ambiguous outputs replay the exact serial ascending-k fp32 FMA
// chain. VALIDATED R12-R15: rel_err 4.888245e-4 (1 flip).
// R16: cleanup = 32 lane-parallel chains/block + double-buffered staging;
//      xconv fused into softmax kernel.

#define M_DIM 4096
#define N_DIM 2048
#define K_DIM 2048

#define SCALE_F 65536.0f
#define THRESH_S 32768.0f
#define AMB_S 0.6f
#define CAP 65536

__device__ float  g_w[(size_t)N_DIM * K_DIM];
__device__ __half g_xh[(size_t)M_DIM * K_DIM];
__device__ __half g_h1[(size_t)N_DIM * K_DIM];
__device__ __half g_h2[(size_t)N_DIM * K_DIM];
__device__ int g_cnt;
__device__ int g_list[CAP];

// ============ kernel 1: XLA softmax replica + limbs + fused x->fp16 =========
__global__ __launch_bounds__(1024) void softmax_rows_kernel(const float* __restrict__ raw,
                                                            const float* __restrict__ x) {
    const int row = blockIdx.x;
    const int tid = threadIdx.x;
    const int lane = tid & 31;
    const int wid = tid >> 5;

    if (row == 0 && tid == 0) g_cnt = 0;

    // fused x conversion: each block converts 4096 x elements (independent work)
    {
        const size_t xi = ((size_t)row * 1024 + tid) * 4;
        const float4 v = *(const float4*)(x + xi);
        __half2 h[2];
        h[0] = __floats2half2_rn(v.x, v.y);
        h[1] = __floats2half2_rn(v.z, v.w);
        *(uint2*)(g_xh + xi) = *(const uint2*)h;
    }

    const float2* __restrict__ r2 =
        reinterpret_cast<const float2*>(raw + (size_t)row * K_DIM);
    float2* __restrict__ w2 = reinterpret_cast<float2*>(g_w + (size_t)row * K_DIM);

    const float2 v = r2[tid];

    __shared__ float s_part[32];
    __shared__ float s_bcast;

    float m = fmaxf(v.x, v.y);
#pragma unroll
    for (int off = 16; off > 0; off >>= 1)
        m = fmaxf(m, __shfl_down_sync(0xffffffffu, m, off));
    if (lane == 0) s_part[wid] = m;
    __syncthreads();
    if (wid == 0) {
        float t = s_part[lane];
#pragma unroll
        for (int off = 16; off > 0; off >>= 1)
            t = fmaxf(t, __shfl_down_sync(0xffffffffu, t, off));
        if (lane == 0) s_bcast = t;
    }
    __syncthreads();
    m = s_bcast;
    __syncthreads();

    const float e0 = expf(v.x - m);
    const float e1 = expf(v.y - m);

    float p = e0 + e1;
#pragma unroll
    for (int off = 16; off > 0; off >>= 1)
        p += __shfl_down_sync(0xffffffffu, p, off);
    if (lane == 0) s_part[wid] = p;
    __syncthreads();
    if (wid == 0) {
        float t = s_part[lane];
#pragma unroll
        for (int off = 16; off > 0; off >>= 1)
            t += __shfl_down_sync(0xffffffffu, t, off);
        if (lane == 0) s_bcast = t;
    }
    __syncthreads();
    const float S = s_bcast;

    float2 w;
    w.x = e0 / S;
    w.y = e1 / S;
    w2[tid] = w;

    const float tx = w.x * SCALE_F;
    const float ty = w.y * SCALE_F;
    const __half ax = __float2half_rn(tx);
    const __half ay = __float2half_rn(ty);
    const __half bx = __float2half_rn(tx - __half2float(ax));
    const __half by = __float2half_rn(ty - __half2float(ay));
    reinterpret_cast<__half2*>(g_h1 + (size_t)row * K_DIM)[tid] = __halves2half2(ax, ay);
    reinterpret_cast<__half2*>(g_h2 + (size_t)row * K_DIM)[tid] = __halves2half2(bx, by);
}

// ===================== kernel 2: HMMA two-limb GEMM, 4-stage cp.async ========
#define SROW 24
#define TILE_H (128 * SROW)
#define TB ((uint32_t)TILE_H * 2)
#define STB (3 * TB)
#define NSTAGE 4
#define SMEM_DYN (NSTAGE * STB)
#define NKT (K_DIM / 16)

__device__ __forceinline__ uint32_t smem_u32(const void* p) {
    uint32_t a;
    asm("{ .reg .u64 t; cvta.to.shared.u64 t, %1; cvt.u32.u64 %0, t; }" : "=r"(a) : "l"(p));
    return a;
}

#define CP16(dst, src) \
    asm volatile("cp.async.cg.shared.global [%0], [%1], 16;" :: "r"(dst), "l"(src))
#define CP_COMMIT() asm volatile("cp.async.commit_group;" ::: "memory")
#define CP_WAIT2()  asm volatile("cp.async.wait_group 2;" ::: "memory")
#define CP_WAIT1()  asm volatile("cp.async.wait_group 1;" ::: "memory")
#define CP_WAIT0()  asm volatile("cp.async.wait_group 0;" ::: "memory")

#define LDSM_X4(r0, r1, r2, r3, a) \
    asm volatile("ldmatrix.sync.aligned.m8n8.x4.shared.b16 {%0,%1,%2,%3}, [%4];" \
                 : "=r"(r0), "=r"(r1), "=r"(r2), "=r"(r3) : "r"(a))
#define LDSM_X2(r0, r1, a) \
    asm volatile("ldmatrix.sync.aligned.m8n8.x2.shared.b16 {%0,%1}, [%2];" \
                 : "=r"(r0), "=r"(r1) : "r"(a))
#define MMA16816(c, a0, a1, a2, a3, b0, b1)                                    \
    asm volatile(                                                              \
        "mma.sync.aligned.m16n8k16.row.col.f32.f16.f16.f32 "                   \
        "{%0,%1,%2,%3}, {%4,%5,%6,%7}, {%8,%9}, {%0,%1,%2,%3};"                \
        : "+f"(c[0]), "+f"(c[1]), "+f"(c[2]), "+f"(c[3])                       \
        : "r"(a0), "r"(a1), "r"(a2), "r"(a3), "r"(b0), "r"(b1))

__global__ __launch_bounds__(256, 2) void mma_gemm_kernel(float* __restrict__ C) {
    extern __shared__ __half dsm[];

    const int tid = threadIdx.x;
    const int wid = tid >> 5;
    const int lane = tid & 31;
    const int wm = wid & 1;
    const int wn = wid >> 1;
    const int bm = blockIdx.y * 128;
    const int bn = blockIdx.x * 128;

    const int lrow = tid >> 1;
    const int lc = (tid & 1) * 8;
    const uint32_t ldst_b = (uint32_t)(lrow * SROW + lc) * 2;

    const __half* __restrict__ Ag = g_xh + (size_t)(bm + lrow) * K_DIM + lc;
    const __half* __restrict__ B1g = g_h1 + (size_t)(bn + lrow) * K_DIM + lc;
    const __half* __restrict__ B2g = g_h2 + (size_t)(bn + lrow) * K_DIM + lc;

    const int a_off = (wm * 64 + (lane & 15)) * SROW + (lane >> 4) * 8;
    const int b_off = (wn * 32 + (lane & 7)) * SROW + ((lane >> 3) & 1) * 8;

    const uint32_t sm0 = smem_u32(dsm);

    float c[16][4];
#pragma unroll
    for (int f = 0; f < 16; ++f)
#pragma unroll
        for (int u = 0; u < 4; ++u) c[f][u] = 0.f;

#pragma unroll
    for (int p = 0; p < NSTAGE - 1; ++p) {
        const uint32_t sbase = sm0 + (uint32_t)p * STB;
        const int ko = p * 16;
        CP16(sbase + 0 * TB + ldst_b, Ag + ko);
        CP16(sbase + 1 * TB + ldst_b, B1g + ko);
        CP16(sbase + 2 * TB + ldst_b, B2g + ko);
        CP_COMMIT();
    }

    for (int kt = 0; kt < NKT; ++kt) {
        if (kt < NKT - 2) { CP_WAIT2(); }
        else if (kt == NKT - 2) { CP_WAIT1(); }
        else { CP_WAIT0(); }
        __syncthreads();

        if (kt + 3 < NKT) {
            const uint32_t sbase = sm0 + (uint32_t)((kt + 3) & 3) * STB;
            const int ko = (kt + 3) * 16;
            CP16(sbase + 0 * TB + ldst_b, Ag + ko);
            CP16(sbase + 1 * TB + ldst_b, B1g + ko);
            CP16(sbase + 2 * TB + ldst_b, B2g + ko);
            CP_COMMIT();
        }

        const uint32_t base = sm0 + (uint32_t)(kt & 3) * STB;
        uint32_t a[4][4];
#pragma unroll
        for (int mi = 0; mi < 4; ++mi)
            LDSM_X4(a[mi][0], a[mi][1], a[mi][2], a[mi][3],
                    base + (uint32_t)(a_off + mi * 16 * SROW) * 2);
        uint32_t b1[4][2], b2[4][2];
#pragma unroll
        for (int ni = 0; ni < 4; ++ni) {
            LDSM_X2(b1[ni][0], b1[ni][1], base + TB + (uint32_t)(b_off + ni * 8 * SROW) * 2);
            LDSM_X2(b2[ni][0], b2[ni][1], base + 2 * TB + (uint32_t)(b_off + ni * 8 * SROW) * 2);
        }

#pragma unroll
        for (int mi = 0; mi < 4; ++mi)
#pragma unroll
            for (int ni = 0; ni < 4; ++ni)
                MMA16816(c[mi * 4 + ni], a[mi][0], a[mi][1], a[mi][2], a[mi][3],
                         b1[ni][0], b1[ni][1]);
#pragma unroll
        for (int mi = 0; mi < 4; ++mi)
#pragma unroll
            for (int ni = 0; ni < 4; ++ni)
                MMA16816(c[mi * 4 + ni], a[mi][0], a[mi][1], a[mi][2], a[mi][3],
                         b2[ni][0], b2[ni][1]);
    }

    const int gl = lane >> 2;
    const int tg = lane & 3;
#pragma unroll
    for (int mi = 0; mi < 4; ++mi) {
#pragma unroll
        for (int ni = 0; ni < 4; ++ni) {
            const float* cc = c[mi * 4 + ni];
            const int r0 = bm + wm * 64 + mi * 16 + gl;
            const int n0 = bn + wn * 32 + ni * 8 + tg * 2;
#pragma unroll
            for (int h = 0; h < 2; ++h) {
                const int r = r0 + h * 8;
                const float v0 = cc[h * 2 + 0];
                const float v1 = cc[h * 2 + 1];
                if (fabsf(v0 - THRESH_S) < AMB_S) {
                    const int ix = atomicAdd(&g_cnt, 1);
                    if (ix < CAP) g_list[ix] = r * N_DIM + n0;
                }
                if (fabsf(v1 - THRESH_S) < AMB_S) {
                    const int ix = atomicAdd(&g_cnt, 1);
                    if (ix < CAP) g_list[ix] = r * N_DIM + n0 + 1;
                }
                float2 o;
                o.x = v0 > THRESH_S ? 1.f : 0.f;
                o.y = v1 > THRESH_S ? 1.f : 0.f;
                *(float2*)&C[(size_t)r * N_DIM + n0] = o;
            }
        }
    }
}

// ===================== kernel 3: lane-parallel exact cleanup ==================
// 32 outputs per block: lane j of warp 0 runs output j's serial ascending-k
// fp32 FMA chain (bit-identical) on 128-element chunks; warps 1-7 stage the
// next chunk (w fp32 + x fp16->fp32, both exact) into the other smem buffer.
// smem stride 129 -> conflict-free lane reads.
#define CB 32          // outputs per block
#define CCH 128        // chunk elements
#define CSTR 129       // smem row stride (floats)
#define CLEAN_SMEM (2 * 2 * CB * CSTR * 4)  // 2 arrays x 2 bufs: 66048 B

__global__ __launch_bounds__(256) void cleanup_kernel(float* __restrict__ C) {
    extern __shared__ float csm[];
    float* swb = csm;                    // [2][CB][CSTR]
    float* sxb = csm + 2 * CB * CSTR;    // [2][CB][CSTR]
    __shared__ int ids[CB];

    int n = g_cnt;
    if (n > CAP) n = CAP;
    const int tid = threadIdx.x;
    const int lane = tid & 31;
    const int wrp = tid >> 5;

    for (int base = blockIdx.x * CB; base < n; base += gridDim.x * CB) {
        const int cnt = min(CB, n - base);
        if (tid < CB) ids[tid] = g_list[base + min(tid, cnt - 1)];
        __syncthreads();

        // ---- stage chunk 0 into buf 0 (all threads) ----
        for (int i = tid; i < CB * CCH; i += 256) {
            const int row = i >> 7;
            const int col = i & 127;
            const int id = ids[row];
            const int o = id & (N_DIM - 1);
            const int b = id >> 11;
            swb[row * CSTR + col] = g_w[(size_t)o * K_DIM + col];
            sxb[row * CSTR + col] = __half2float(g_xh[(size_t)b * K_DIM + col]);
        }
        __syncthreads();

        float acc = 0.f;
#pragma unroll
        for (int ch = 0; ch < K_DIM / CCH; ++ch) {
            const int cur = ch & 1;
            if (wrp == 0) {
                // 32 serial chains, one per lane, strictly ascending k
                const float* swp = swb + cur * CB * CSTR + lane * CSTR;
                const float* sxp = sxb + cur * CB * CSTR + lane * CSTR;
#pragma unroll 32
                for (int k = 0; k < CCH; ++k)
                    acc = fmaf(sxp[k], swp[k], acc);
            } else if (ch + 1 < K_DIM / CCH) {
                // warps 1-7 stage chunk ch+1 into the other buffer
                const int c0 = (ch + 1) * CCH;
                const int nxt = (ch + 1) & 1;
                for (int i = tid - 32; i < CB * CCH; i += 224) {
                    const int row = i >> 7;
                    const int col = i & 127;
                    const int id = ids[row];
                    const int o = id & (N_DIM - 1);
                    const int b = id >> 11;
                    swb[nxt * CB * CSTR + row * CSTR + col] =
                        g_w[(size_t)o * K_DIM + c0 + col];
                    sxb[nxt * CB * CSTR + row * CSTR + col] =
                        __half2float(g_xh[(size_t)b * K_DIM + c0 + col]);
                }
            }
            __syncthreads();
        }

        if (wrp == 0 && lane < cnt)
            C[ids[lane]] = acc > 0.5f ? 1.f : 0.f;
        __syncthreads();
    }
}

// ---------------------------------------------------------------------------
extern "C" void kernel_launch(void* const* d_in, const int* in_sizes, int n_in,
                              void* d_out, int out_size) {
    const float* x = (const float*)d_in[0];      // [4096, 2048]
    const float* raw_w = (const float*)d_in[1];  // [2048, 2048]
    float* out = (float*)d_out;                  // [4096, 2048]

    cudaFuncSetAttribute(mma_gemm_kernel,
                         cudaFuncAttributeMaxDynamicSharedMemorySize, SMEM_DYN);
    cudaFuncSetAttribute(cleanup_kernel,
                         cudaFuncAttributeMaxDynamicSharedMemorySize, CLEAN_SMEM);

    softmax_rows_kernel<<<N_DIM, 1024>>>(raw_w, x);

    dim3 grid(N_DIM / 128, M_DIM / 128);  // (16, 32)
    mma_gemm_kernel<<<grid, 256, SMEM_DYN>>>(out);

    cleanup_kernel<<<148, 256, CLEAN_SMEM>>>(out);
}

// round 17
// speedup vs baseline: 1.0995x; 1.0995x over previous
#include <cuda_runtime.h>
#include <cuda_fp16.h>
#include <cstdint>

// out[b,o] = ( x @ softmax(W,axis=1)^T > 0.5 )
// Two-pass: (1) HMMA two-limb GEMM (scale 2^16): limb1 fp32-acc, limb2
// fp16-acc (error budget 0.08 << 0.6 window); outputs with |S1-32768|>0.6
// provably match the reference fp32 serial chain. (2) ambiguous outputs
// replay the exact serial ascending-k fp32 FMA chain.
// VALIDATED R12-R16: rel_err 4.888245e-4 (1 flip).
// R17: revert cleanup to R15 block-per-output (R16 lane-parallel regressed);
//      keep xconv fused into softmax; limb2 GEMM uses f16 accumulators.

#define M_DIM 4096
#define N_DIM 2048
#define K_DIM 2048

#define SCALE_F 65536.0f
#define THRESH_S 32768.0f
#define AMB_S 0.6f
#define CAP 65536

__device__ float  g_w[(size_t)N_DIM * K_DIM];
__device__ __half g_xh[(size_t)M_DIM * K_DIM];
__device__ __half g_h1[(size_t)N_DIM * K_DIM];
__device__ __half g_h2[(size_t)N_DIM * K_DIM];
__device__ int g_cnt;
__device__ int g_list[CAP];

// ============ kernel 1: XLA softmax replica + limbs + fused x->fp16 =========
__global__ __launch_bounds__(1024) void softmax_rows_kernel(const float* __restrict__ raw,
                                                            const float* __restrict__ x) {
    const int row = blockIdx.x;
    const int tid = threadIdx.x;
    const int lane = tid & 31;
    const int wid = tid >> 5;

    if (row == 0 && tid == 0) g_cnt = 0;

    {   // fused x conversion: each block converts 4096 x elements
        const size_t xi = ((size_t)row * 1024 + tid) * 4;
        const float4 v = *(const float4*)(x + xi);
        __half2 h[2];
        h[0] = __floats2half2_rn(v.x, v.y);
        h[1] = __floats2half2_rn(v.z, v.w);
        *(uint2*)(g_xh + xi) = *(const uint2*)h;
    }

    const float2* __restrict__ r2 =
        reinterpret_cast<const float2*>(raw + (size_t)row * K_DIM);
    float2* __restrict__ w2 = reinterpret_cast<float2*>(g_w + (size_t)row * K_DIM);

    const float2 v = r2[tid];

    __shared__ float s_part[32];
    __shared__ float s_bcast;

    float m = fmaxf(v.x, v.y);
#pragma unroll
    for (int off = 16; off > 0; off >>= 1)
        m = fmaxf(m, __shfl_down_sync(0xffffffffu, m, off));
    if (lane == 0) s_part[wid] = m;
    __syncthreads();
    if (wid == 0) {
        float t = s_part[lane];
#pragma unroll
        for (int off = 16; off > 0; off >>= 1)
            t = fmaxf(t, __shfl_down_sync(0xffffffffu, t, off));
        if (lane == 0) s_bcast = t;
    }
    __syncthreads();
    m = s_bcast;
    __syncthreads();

    const float e0 = expf(v.x - m);
    const float e1 = expf(v.y - m);

    float p = e0 + e1;
#pragma unroll
    for (int off = 16; off > 0; off >>= 1)
        p += __shfl_down_sync(0xffffffffu, p, off);
    if (lane == 0) s_part[wid] = p;
    __syncthreads();
    if (wid == 0) {
        float t = s_part[lane];
#pragma unroll
        for (int off = 16; off > 0; off >>= 1)
            t += __shfl_down_sync(0xffffffffu, t, off);
        if (lane == 0) s_bcast = t;
    }
    __syncthreads();
    const float S = s_bcast;

    float2 w;
    w.x = e0 / S;
    w.y = e1 / S;
    w2[tid] = w;

    const float tx = w.x * SCALE_F;
    const float ty = w.y * SCALE_F;
    const __half ax = __float2half_rn(tx);
    const __half ay = __float2half_rn(ty);
    const __half bx = __float2half_rn(tx - __half2float(ax));
    const __half by = __float2half_rn(ty - __half2float(ay));
    reinterpret_cast<__half2*>(g_h1 + (size_t)row * K_DIM)[tid] = __halves2half2(ax, ay);
    reinterpret_cast<__half2*>(g_h2 + (size_t)row * K_DIM)[tid] = __halves2half2(bx, by);
}

// ===================== kernel 2: HMMA two-limb GEMM, 4-stage cp.async ========
// limb1: mma f32 accum (exact-ish); limb2: mma f16 accum (sigma ~0.006 scaled).
#define SROW 24
#define TILE_H (128 * SROW)
#define TB ((uint32_t)TILE_H * 2)
#define STB (3 * TB)
#define NSTAGE 4
#define SMEM_DYN (NSTAGE * STB)
#define NKT (K_DIM / 16)

__device__ __forceinline__ uint32_t smem_u32(const void* p) {
    uint32_t a;
    asm("{ .reg .u64 t; cvta.to.shared.u64 t, %1; cvt.u32.u64 %0, t; }" : "=r"(a) : "l"(p));
    return a;
}

#define CP16(dst, src) \
    asm volatile("cp.async.cg.shared.global [%0], [%1], 16;" :: "r"(dst), "l"(src))
#define CP_COMMIT() asm volatile("cp.async.commit_group;" ::: "memory")
#define CP_WAIT2()  asm volatile("cp.async.wait_group 2;" ::: "memory")
#define CP_WAIT1()  asm volatile("cp.async.wait_group 1;" ::: "memory")
#define CP_WAIT0()  asm volatile("cp.async.wait_group 0;" ::: "memory")

#define LDSM_X4(r0, r1, r2, r3, a) \
    asm volatile("ldmatrix.sync.aligned.m8n8.x4.shared.b16 {%0,%1,%2,%3}, [%4];" \
                 : "=r"(r0), "=r"(r1), "=r"(r2), "=r"(r3) : "r"(a))
#define LDSM_X2(r0, r1, a) \
    asm volatile("ldmatrix.sync.aligned.m8n8.x2.shared.b16 {%0,%1}, [%2];" \
                 : "=r"(r0), "=r"(r1) : "r"(a))
#define MMA16816(c, a0, a1, a2, a3, b0, b1)                                    \
    asm volatile(                                                              \
        "mma.sync.aligned.m16n8k16.row.col.f32.f16.f16.f32 "                   \
        "{%0,%1,%2,%3}, {%4,%5,%6,%7}, {%8,%9}, {%0,%1,%2,%3};"                \
        : "+f"(c[0]), "+f"(c[1]), "+f"(c[2]), "+f"(c[3])                       \
        : "r"(a0), "r"(a1), "r"(a2), "r"(a3), "r"(b0), "r"(b1))
#define MMA16816_H(d, a0, a1, a2, a3, b0, b1)                                  \
    asm volatile(                                                              \
        "mma.sync.aligned.m16n8k16.row.col.f16.f16.f16.f16 "                   \
        "{%0,%1}, {%2,%3,%4,%5}, {%6,%7}, {%0,%1};"                            \
        : "+r"(d[0]), "+r"(d[1])                                               \
        : "r"(a0), "r"(a1), "r"(a2), "r"(a3), "r"(b0), "r"(b1))

__global__ __launch_bounds__(256, 2) void mma_gemm_kernel(float* __restrict__ C) {
    extern __shared__ __half dsm[];

    const int tid = threadIdx.x;
    const int wid = tid >> 5;
    const int lane = tid & 31;
    const int wm = wid & 1;
    const int wn = wid >> 1;
    const int bm = blockIdx.y * 128;
    const int bn = blockIdx.x * 128;

    const int lrow = tid >> 1;
    const int lc = (tid & 1) * 8;
    const uint32_t ldst_b = (uint32_t)(lrow * SROW + lc) * 2;

    const __half* __restrict__ Ag = g_xh + (size_t)(bm + lrow) * K_DIM + lc;
    const __half* __restrict__ B1g = g_h1 + (size_t)(bn + lrow) * K_DIM + lc;
    const __half* __restrict__ B2g = g_h2 + (size_t)(bn + lrow) * K_DIM + lc;

    const int a_off = (wm * 64 + (lane & 15)) * SROW + (lane >> 4) * 8;
    const int b_off = (wn * 32 + (lane & 7)) * SROW + ((lane >> 3) & 1) * 8;

    const uint32_t sm0 = smem_u32(dsm);

    float c1[16][4];       // limb1, fp32 accum
    uint32_t c2[16][2];    // limb2, f16x2 accum
#pragma unroll
    for (int f = 0; f < 16; ++f) {
#pragma unroll
        for (int u = 0; u < 4; ++u) c1[f][u] = 0.f;
        c2[f][0] = 0u; c2[f][1] = 0u;
    }

#pragma unroll
    for (int p = 0; p < NSTAGE - 1; ++p) {
        const uint32_t sbase = sm0 + (uint32_t)p * STB;
        const int ko = p * 16;
        CP16(sbase + 0 * TB + ldst_b, Ag + ko);
        CP16(sbase + 1 * TB + ldst_b, B1g + ko);
        CP16(sbase + 2 * TB + ldst_b, B2g + ko);
        CP_COMMIT();
    }

    for (int kt = 0; kt < NKT; ++kt) {
        if (kt < NKT - 2) { CP_WAIT2(); }
        else if (kt == NKT - 2) { CP_WAIT1(); }
        else { CP_WAIT0(); }
        __syncthreads();

        if (kt + 3 < NKT) {
            const uint32_t sbase = sm0 + (uint32_t)((kt + 3) & 3) * STB;
            const int ko = (kt + 3) * 16;
            CP16(sbase + 0 * TB + ldst_b, Ag + ko);
            CP16(sbase + 1 * TB + ldst_b, B1g + ko);
            CP16(sbase + 2 * TB + ldst_b, B2g + ko);
            CP_COMMIT();
        }

        const uint32_t base = sm0 + (uint32_t)(kt & 3) * STB;
        uint32_t a[4][4];
#pragma unroll
        for (int mi = 0; mi < 4; ++mi)
            LDSM_X4(a[mi][0], a[mi][1], a[mi][2], a[mi][3],
                    base + (uint32_t)(a_off + mi * 16 * SROW) * 2);
        uint32_t b1[4][2], b2[4][2];
#pragma unroll
        for (int ni = 0; ni < 4; ++ni) {
            LDSM_X2(b1[ni][0], b1[ni][1], base + TB + (uint32_t)(b_off + ni * 8 * SROW) * 2);
            LDSM_X2(b2[ni][0], b2[ni][1], base + 2 * TB + (uint32_t)(b_off + ni * 8 * SROW) * 2);
        }

#pragma unroll
        for (int mi = 0; mi < 4; ++mi)
#pragma unroll
            for (int ni = 0; ni < 4; ++ni)
                MMA16816(c1[mi * 4 + ni], a[mi][0], a[mi][1], a[mi][2], a[mi][3],
                         b1[ni][0], b1[ni][1]);
#pragma unroll
        for (int mi = 0; mi < 4; ++mi)
#pragma unroll
            for (int ni = 0; ni < 4; ++ni)
                MMA16816_H(c2[mi * 4 + ni], a[mi][0], a[mi][1], a[mi][2], a[mi][3],
                           b2[ni][0], b2[ni][1]);
    }

    // Epilogue: S1 = c1 + float(c2). f16 D layout: d0={r0c0,r0c1}, d1={r1c0,r1c1}.
    const int gl = lane >> 2;
    const int tg = lane & 3;
#pragma unroll
    for (int mi = 0; mi < 4; ++mi) {
#pragma unroll
        for (int ni = 0; ni < 4; ++ni) {
            const float* cc = c1[mi * 4 + ni];
            const int r0 = bm + wm * 64 + mi * 16 + gl;
            const int n0 = bn + wn * 32 + ni * 8 + tg * 2;
#pragma unroll
            for (int h = 0; h < 2; ++h) {
                const int r = r0 + h * 8;
                const __half2 l2 = *(const __half2*)&c2[mi * 4 + ni][h];
                const float v0 = cc[h * 2 + 0] + __low2float(l2);
                const float v1 = cc[h * 2 + 1] + __high2float(l2);
                if (fabsf(v0 - THRESH_S) < AMB_S) {
                    const int ix = atomicAdd(&g_cnt, 1);
                    if (ix < CAP) g_list[ix] = r * N_DIM + n0;
                }
                if (fabsf(v1 - THRESH_S) < AMB_S) {
                    const int ix = atomicAdd(&g_cnt, 1);
                    if (ix < CAP) g_list[ix] = r * N_DIM + n0 + 1;
                }
                float2 o;
                o.x = v0 > THRESH_S ? 1.f : 0.f;
                o.y = v1 > THRESH_S ? 1.f : 0.f;
                *(float2*)&C[(size_t)r * N_DIM + n0] = o;
            }
        }
    }
}

// ===================== kernel 3: block-per-output exact cleanup (R15) ========
__global__ __launch_bounds__(256) void cleanup_kernel(const float* __restrict__ x,
                                                      float* __restrict__ C) {
    __shared__ float sw[K_DIM];
    __shared__ float sx[K_DIM];

    int n = g_cnt;
    if (n > CAP) n = CAP;
    const int tid = threadIdx.x;

    for (int t = blockIdx.x; t < n; t += gridDim.x) {
        const int id = g_list[t];
        const int b = id >> 11;
        const int o = id & (N_DIM - 1);
        const float4* __restrict__ xr = (const float4*)(x + (size_t)b * K_DIM);
        const float4* __restrict__ wr = (const float4*)(g_w + (size_t)o * K_DIM);

#pragma unroll
        for (int i = 0; i < 2; ++i) {
            const int idx = tid + i * 256;
            ((float4*)sx)[idx] = xr[idx];
            ((float4*)sw)[idx] = wr[idx];
        }
        __syncthreads();
        if (tid == 0) {
            float acc = 0.f;
#pragma unroll 16
            for (int k = 0; k < K_DIM; ++k)  // strictly ascending serial chain
                acc = fmaf(sx[k], sw[k], acc);
            C[id] = acc > 0.5f ? 1.f : 0.f;
        }
        __syncthreads();
    }
}

// ---------------------------------------------------------------------------
extern "C" void kernel_launch(void* const* d_in, const int* in_sizes, int n_in,
                              void* d_out, int out_size) {
    const float* x = (const float*)d_in[0];      // [4096, 2048]
    const float* raw_w = (const float*)d_in[1];  // [2048, 2048]
    float* out = (float*)d_out;                  // [4096, 2048]

    cudaFuncSetAttribute(mma_gemm_kernel,
                         cudaFuncAttributeMaxDynamicSharedMemorySize, SMEM_DYN);

    softmax_rows_kernel<<<N_DIM, 1024>>>(raw_w, x);

    dim3 grid(N_DIM / 128, M_DIM / 128);  // (16, 32)
    mma_gemm_kernel<<<grid, 256, SMEM_DYN>>>(out);

    cleanup_kernel<<<2048, 256>>>(x, out);
}